// round 9
// baseline (speedup 1.0000x reference)
#include <cuda_runtime.h>
#include <cuda_bf16.h>
#include <math.h>
#include <stdint.h>

#define BB 32
#define TT 1024
#define CC 256
#define HH 64

// ---------------- attention tiling ----------------
#define AQT 128         // q rows per CTA (16 per warp, 8 warps)
#define AKT 64          // keys per tile
#define KSTR 68         // K padded stride (words)
#define VSTR 72         // V padded stride
#define QSTR 68         // Q/P padded stride
#define KBUF (AKT*KSTR)
#define VBUF (AKT*VSTR)
#define ATT_SMEM ((2*KBUF + 2*VBUF + AQT*QSTR) * 4)    // 106496 B

// ---------------- projection tiling (bf16x3 split MMA) ----------------
#define PRT 64
#define PKC 64
#define XSTR 36

__device__ float g_q[BB * TT * HH];
__device__ float g_k[BB * TT * HH];
__device__ float g_v[BB * TT * HH];

// ---------------------------------------------------------------------------
__device__ __forceinline__ uint32_t f2tf(float f) {
    uint32_t u;
    asm("cvt.rna.tf32.f32 %0, %1;" : "=r"(u) : "f"(f));
    return u;
}

__device__ __forceinline__ void mma_tf32(float d[4], const uint32_t a[4],
                                         const uint32_t b0, const uint32_t b1) {
    asm("mma.sync.aligned.m16n8k8.row.col.f32.tf32.tf32.f32 "
        "{%0,%1,%2,%3}, {%4,%5,%6,%7}, {%8,%9}, {%0,%1,%2,%3};"
        : "+f"(d[0]), "+f"(d[1]), "+f"(d[2]), "+f"(d[3])
        : "r"(a[0]), "r"(a[1]), "r"(a[2]), "r"(a[3]), "r"(b0), "r"(b1));
}

__device__ __forceinline__ void mma_bf16(float d[4], const uint32_t a[4],
                                         const uint32_t b0, const uint32_t b1) {
    asm("mma.sync.aligned.m16n8k16.row.col.f32.bf16.bf16.f32 "
        "{%0,%1,%2,%3}, {%4,%5,%6,%7}, {%8,%9}, {%0,%1,%2,%3};"
        : "+f"(d[0]), "+f"(d[1]), "+f"(d[2]), "+f"(d[3])
        : "r"(a[0]), "r"(a[1]), "r"(a[2]), "r"(a[3]), "r"(b0), "r"(b1));
}

__device__ __forceinline__ uint32_t pack_bf2(float a, float b) {
    __nv_bfloat162 t = __floats2bfloat162_rn(a, b);
    return *(uint32_t*)&t;
}
__device__ __forceinline__ float bf_hi(float x) {
    return __bfloat162float(__float2bfloat16_rn(x));
}

__device__ __forceinline__ void cp16(uint32_t dst, const void* src) {
    asm volatile("cp.async.cg.shared.global [%0], [%1], 16;" :: "r"(dst), "l"(src));
}

// ---------------------------------------------------------------------------
// Projection GEMM, bf16x3 split — unchanged from the measured R7 win.
// ---------------------------------------------------------------------------
__global__ __launch_bounds__(128) void proj_kernel(
    const float* __restrict__ x,
    const float* __restrict__ Wq,
    const float* __restrict__ Wk,
    const float* __restrict__ Wv)
{
    __shared__ uint32_t Xh[PRT * XSTR], Xl[PRT * XSTR];
    __shared__ uint32_t Wh[HH * XSTR],  Wl[HH * XSTR];

    const int wsel = blockIdx.y;
    const float* W  = (wsel == 0) ? Wq : (wsel == 1) ? Wk : Wv;
    float* dst      = (wsel == 0) ? g_q : (wsel == 1) ? g_k : g_v;

    const int tid  = threadIdx.x;
    const int lane = tid & 31, warp = tid >> 5;
    const int r = lane >> 2, c = lane & 3;
    const int w16 = warp * 16;
    const size_t row0 = (size_t)blockIdx.x * PRT;

    float acc[8][4];
#pragma unroll
    for (int j = 0; j < 8; ++j)
#pragma unroll
        for (int i = 0; i < 4; ++i) acc[j][i] = 0.f;

    for (int kb = 0; kb < CC; kb += PKC) {
        if (kb) __syncthreads();
#pragma unroll
        for (int it = 0; it < 8; ++it) {
            int f = it * 128 + tid;
            int row = f >> 4, cf = (f & 15) * 4;
            float4 v = *(const float4*)&x[(row0 + row) * CC + kb + cf];
            float hx = bf_hi(v.x), hy = bf_hi(v.y), hz = bf_hi(v.z), hw = bf_hi(v.w);
            uint2 hi = {pack_bf2(hx, hy), pack_bf2(hz, hw)};
            uint2 lo = {pack_bf2(v.x - hx, v.y - hy), pack_bf2(v.z - hz, v.w - hw)};
            int p = row * XSTR + cf / 2;
            *(uint2*)&Xh[p] = hi;
            *(uint2*)&Xl[p] = lo;
        }
#pragma unroll
        for (int it = 0; it < 4; ++it) {
            int idx = it * 128 + tid;
            int kp = idx >> 4, n0 = (idx & 15) * 4;
            float4 e = *(const float4*)&W[(kb + 2 * kp)     * HH + n0];
            float4 o = *(const float4*)&W[(kb + 2 * kp + 1) * HH + n0];
            float he[4] = {bf_hi(e.x), bf_hi(e.y), bf_hi(e.z), bf_hi(e.w)};
            float ho[4] = {bf_hi(o.x), bf_hi(o.y), bf_hi(o.z), bf_hi(o.w)};
            float ev[4] = {e.x, e.y, e.z, e.w}, ov[4] = {o.x, o.y, o.z, o.w};
#pragma unroll
            for (int i = 0; i < 4; ++i) {
                Wh[(n0 + i) * XSTR + kp] = pack_bf2(he[i], ho[i]);
                Wl[(n0 + i) * XSTR + kp] = pack_bf2(ev[i] - he[i], ov[i] - ho[i]);
            }
        }
        __syncthreads();

#pragma unroll
        for (int ks = 0; ks < 4; ++ks) {
            const int kp0 = 8 * ks;
            uint32_t ah[4], al[4];
            ah[0] = Xh[(w16 + r)     * XSTR + kp0 + c];
            ah[1] = Xh[(w16 + r + 8) * XSTR + kp0 + c];
            ah[2] = Xh[(w16 + r)     * XSTR + kp0 + c + 4];
            ah[3] = Xh[(w16 + r + 8) * XSTR + kp0 + c + 4];
            al[0] = Xl[(w16 + r)     * XSTR + kp0 + c];
            al[1] = Xl[(w16 + r + 8) * XSTR + kp0 + c];
            al[2] = Xl[(w16 + r)     * XSTR + kp0 + c + 4];
            al[3] = Xl[(w16 + r + 8) * XSTR + kp0 + c + 4];
#pragma unroll
            for (int j = 0; j < 8; ++j) {
                const int nrow = (8 * j + r) * XSTR + kp0;
                uint32_t bh0 = Wh[nrow + c], bh1 = Wh[nrow + c + 4];
                uint32_t bl0 = Wl[nrow + c], bl1 = Wl[nrow + c + 4];
                mma_bf16(acc[j], ah, bh0, bh1);
                mma_bf16(acc[j], ah, bl0, bl1);
                mma_bf16(acc[j], al, bh0, bh1);
            }
        }
    }

#pragma unroll
    for (int j = 0; j < 8; ++j) {
        float2 o0 = {acc[j][0], acc[j][1]};
        float2 o1 = {acc[j][2], acc[j][3]};
        *(float2*)&dst[(row0 + w16 + r)     * HH + 8 * j + 2 * c] = o0;
        *(float2*)&dst[(row0 + w16 + r + 8) * HH + 8 * j + 2 * c] = o1;
    }
}

// ---------------------------------------------------------------------------
// Flash attention: 8 warps, Q tile 128, cp.async double-buffered K/V (raw
// fp32 bits into tf32 MMA — HW truncates mantissa). Warp-local softmax and
// P staging as before; warps fully below the diagonal skip masked tiles.
// ---------------------------------------------------------------------------
__global__ __launch_bounds__(256, 2) void attn_kernel(
    float* __restrict__ out, float scale)
{
    extern __shared__ uint32_t smu[];
    uint32_t* Qs = smu + 2 * KBUF + 2 * VBUF;     // [AQT][QSTR], becomes Psh
    const uint32_t smem_base = (uint32_t)__cvta_generic_to_shared(smu);

    const int b = blockIdx.y;
    const int bx = blockIdx.x;
    const int qtile = (bx < 4) ? bx : (11 - bx);  // pair-balanced map
    const int tid  = threadIdx.x;
    const int lane = tid & 31, warp = tid >> 5;
    const int r = lane >> 2, c = lane & 3;
    const int w16 = warp * 16;

    const float* kg0 = g_k + (size_t)b * TT * HH;
    const float* vg0 = g_v + (size_t)b * TT * HH;
    const int nt = 2 * (qtile + 1);

    // ---- prologue: issue async K/V tile 0 into buffer 0 ----
#pragma unroll
    for (int it = 0; it < 4; ++it) {
        int f = it * 256 + tid;
        int row = f >> 4, cf = (f & 15) * 4;
        cp16(smem_base + (row * KSTR + cf) * 4,              kg0 + row * HH + cf);
        cp16(smem_base + (2 * KBUF + row * VSTR + cf) * 4,   vg0 + row * HH + cf);
    }
    asm volatile("cp.async.commit_group;");

    // ---- stage Q (scaled, tf32) ----
    {
        const float* qg = g_q + ((size_t)b * TT + (size_t)qtile * AQT) * HH;
#pragma unroll
        for (int it = 0; it < 8; ++it) {
            int f = it * 256 + tid;
            int row = f >> 4, cf = (f & 15) * 4;
            float4 v = *(const float4*)&qg[row * HH + cf];
            uint4 u = {f2tf(v.x * scale), f2tf(v.y * scale),
                       f2tf(v.z * scale), f2tf(v.w * scale)};
            *(uint4*)&Qs[row * QSTR + cf] = u;
        }
    }
    __syncthreads();

    uint32_t qf[8][4];
#pragma unroll
    for (int ks = 0; ks < 8; ++ks) {
        qf[ks][0] = Qs[(w16 + r)     * QSTR + 8 * ks + c];
        qf[ks][1] = Qs[(w16 + r + 8) * QSTR + 8 * ks + c];
        qf[ks][2] = Qs[(w16 + r)     * QSTR + 8 * ks + c + 4];
        qf[ks][3] = Qs[(w16 + r + 8) * QSTR + 8 * ks + c + 4];
    }

    float O[8][4];
#pragma unroll
    for (int j = 0; j < 8; ++j)
#pragma unroll
        for (int i = 0; i < 4; ++i) O[j][i] = 0.f;
    float m0 = -1e30f, m1 = -1e30f, l0 = 0.f, l1 = 0.f;

    const int wrow_lo = qtile * AQT + w16;        // warp's lowest q row
    const int row0g = wrow_lo + r;
    const int row1g = row0g + 8;

    for (int kt = 0; kt < nt; ++kt) {
        const int kbase = kt * AKT;
        const int cur = kt & 1;
        __syncthreads();   // all reads of buf (kt+1)&1 done (kt=0: qf loads done)

        if (kt + 1 < nt) {
            const int nb = (kt + 1) & 1;
            const float* kg = kg0 + (size_t)(kbase + AKT) * HH;
            const float* vg = vg0 + (size_t)(kbase + AKT) * HH;
#pragma unroll
            for (int it = 0; it < 4; ++it) {
                int f = it * 256 + tid;
                int row = f >> 4, cf = (f & 15) * 4;
                cp16(smem_base + (nb * KBUF + row * KSTR + cf) * 4,           kg + row * HH + cf);
                cp16(smem_base + (2 * KBUF + nb * VBUF + row * VSTR + cf) * 4, vg + row * HH + cf);
            }
            asm volatile("cp.async.commit_group;");
            asm volatile("cp.async.wait_group 1;");
        } else {
            asm volatile("cp.async.wait_group 0;");
        }
        __syncthreads();   // staged data visible to all warps

        if (kbase > wrow_lo + 15) continue;        // warp fully above diag: skip
        const uint32_t* Kc = smu + cur * KBUF;
        const uint32_t* Vc = smu + 2 * KBUF + cur * VBUF;

        float S[8][4];
#pragma unroll
        for (int j = 0; j < 8; ++j)
#pragma unroll
            for (int i = 0; i < 4; ++i) S[j][i] = 0.f;

#pragma unroll
        for (int ks = 0; ks < 8; ++ks) {
#pragma unroll
            for (int j = 0; j < 8; ++j) {
                uint32_t b0 = Kc[(8 * j + r) * KSTR + 8 * ks + c];
                uint32_t b1 = Kc[(8 * j + r) * KSTR + 8 * ks + c + 4];
                mma_tf32(S[j], qf[ks], b0, b1);
            }
        }

        if (kbase + AKT - 1 > wrow_lo) {           // tile touches the diagonal
#pragma unroll
            for (int j = 0; j < 8; ++j) {
                int col = kbase + 8 * j + 2 * c;
                if (col     > row0g) S[j][0] = -1e30f;
                if (col + 1 > row0g) S[j][1] = -1e30f;
                if (col     > row1g) S[j][2] = -1e30f;
                if (col + 1 > row1g) S[j][3] = -1e30f;
            }
        }

        float mt0 = -1e30f, mt1 = -1e30f;
#pragma unroll
        for (int j = 0; j < 8; ++j) {
            mt0 = fmaxf(mt0, fmaxf(S[j][0], S[j][1]));
            mt1 = fmaxf(mt1, fmaxf(S[j][2], S[j][3]));
        }
#pragma unroll
        for (int off = 1; off < 4; off <<= 1) {
            mt0 = fmaxf(mt0, __shfl_xor_sync(0xffffffffu, mt0, off));
            mt1 = fmaxf(mt1, __shfl_xor_sync(0xffffffffu, mt1, off));
        }
        const float mn0 = fmaxf(m0, mt0), mn1 = fmaxf(m1, mt1);
        const float cr0 = __expf(m0 - mn0), cr1 = __expf(m1 - mn1);
        m0 = mn0; m1 = mn1;

        float ls0 = 0.f, ls1 = 0.f;
#pragma unroll
        for (int j = 0; j < 8; ++j) {
            float p0 = __expf(S[j][0] - mn0);
            float p1 = __expf(S[j][1] - mn0);
            float p2 = __expf(S[j][2] - mn1);
            float p3 = __expf(S[j][3] - mn1);
            ls0 += p0 + p1; ls1 += p2 + p3;
            uint2 u01 = {f2tf(p0), f2tf(p1)};
            uint2 u23 = {f2tf(p2), f2tf(p3)};
            *(uint2*)&Qs[(w16 + r)     * QSTR + 8 * j + 2 * c] = u01;
            *(uint2*)&Qs[(w16 + r + 8) * QSTR + 8 * j + 2 * c] = u23;
        }
#pragma unroll
        for (int off = 1; off < 4; off <<= 1) {
            ls0 += __shfl_xor_sync(0xffffffffu, ls0, off);
            ls1 += __shfl_xor_sync(0xffffffffu, ls1, off);
        }
        l0 = l0 * cr0 + ls0;
        l1 = l1 * cr1 + ls1;
#pragma unroll
        for (int j = 0; j < 8; ++j) {
            O[j][0] *= cr0; O[j][1] *= cr0;
            O[j][2] *= cr1; O[j][3] *= cr1;
        }
        __syncwarp();       // P visible within the warp

#pragma unroll
        for (int ks = 0; ks < 8; ++ks) {
            uint32_t pf[4];
            pf[0] = Qs[(w16 + r)     * QSTR + 8 * ks + c];
            pf[1] = Qs[(w16 + r + 8) * QSTR + 8 * ks + c];
            pf[2] = Qs[(w16 + r)     * QSTR + 8 * ks + c + 4];
            pf[3] = Qs[(w16 + r + 8) * QSTR + 8 * ks + c + 4];
#pragma unroll
            for (int j = 0; j < 8; ++j) {
                uint32_t b0 = Vc[(8 * ks + c)     * VSTR + 8 * j + r];
                uint32_t b1 = Vc[(8 * ks + c + 4) * VSTR + 8 * j + r];
                mma_tf32(O[j], pf, b0, b1);
            }
        }
        __syncwarp();       // PV reads done before this warp's next P write
    }

    const float inv0 = 1.f / l0, inv1 = 1.f / l1;
    float* og = out + ((size_t)b * TT + (size_t)qtile * AQT) * HH;
#pragma unroll
    for (int j = 0; j < 8; ++j) {
        float2 o0 = {O[j][0] * inv0, O[j][1] * inv0};
        float2 o1 = {O[j][2] * inv1, O[j][3] * inv1};
        *(float2*)&og[(w16 + r)     * HH + 8 * j + 2 * c] = o0;
        *(float2*)&og[(w16 + r + 8) * HH + 8 * j + 2 * c] = o1;
    }
}

// ---------------------------------------------------------------------------
extern "C" void kernel_launch(void* const* d_in, const int* in_sizes, int n_in,
                              void* d_out, int out_size)
{
    const float* x  = (const float*)d_in[0];
    const float* Wq = (const float*)d_in[1];
    const float* Wk = (const float*)d_in[2];
    const float* Wv = (const float*)d_in[3];
    float* out = (float*)d_out;

    const float scale = (float)pow(256.0, -0.666);

    cudaFuncSetAttribute(attn_kernel,
                         cudaFuncAttributeMaxDynamicSharedMemorySize, ATT_SMEM);

    dim3 pgrid((BB * TT) / PRT, 3);
    proj_kernel<<<pgrid, 128>>>(x, Wq, Wk, Wv);

    dim3 agrid(TT / AQT, BB);
    attn_kernel<<<agrid, 256, ATT_SMEM>>>(out, scale);
}

// round 10
// speedup vs baseline: 1.3563x; 1.3563x over previous
#include <cuda_runtime.h>
#include <cuda_bf16.h>
#include <cuda_fp16.h>
#include <math.h>
#include <stdint.h>

#define BB 32
#define TT 1024
#define CC 256
#define HH 64

// ---------------- attention tiling (fp16 mma + ldmatrix) ----------------
#define AQ 64            // q rows per CTA (16 per warp, 4 warps)
#define AKT 64           // keys per tile
#define KROW 144         // bytes per smem row: 64 fp16 + 8 pad (=> banks 4r+c)
#define TILE_SM (64 * KROW)              // 9216 B per tile buffer
#define ATT_SMEM (3 * TILE_SM)           // Q + K + V = 27648 B

// ---------------- projection tiling (bf16x3 split MMA, frozen R7) -------
#define PRT 64
#define PKC 64
#define XSTR 36

__device__ float g_q[BB * TT * HH];
__device__ float g_k[BB * TT * HH];
__device__ float g_v[BB * TT * HH];

// ---------------------------------------------------------------------------
__device__ __forceinline__ void mma_bf16(float d[4], const uint32_t a[4],
                                         const uint32_t b0, const uint32_t b1) {
    asm("mma.sync.aligned.m16n8k16.row.col.f32.bf16.bf16.f32 "
        "{%0,%1,%2,%3}, {%4,%5,%6,%7}, {%8,%9}, {%0,%1,%2,%3};"
        : "+f"(d[0]), "+f"(d[1]), "+f"(d[2]), "+f"(d[3])
        : "r"(a[0]), "r"(a[1]), "r"(a[2]), "r"(a[3]), "r"(b0), "r"(b1));
}

__device__ __forceinline__ void mma_f16(float d[4], const uint32_t a[4],
                                        const uint32_t b0, const uint32_t b1) {
    asm("mma.sync.aligned.m16n8k16.row.col.f32.f16.f16.f32 "
        "{%0,%1,%2,%3}, {%4,%5,%6,%7}, {%8,%9}, {%0,%1,%2,%3};"
        : "+f"(d[0]), "+f"(d[1]), "+f"(d[2]), "+f"(d[3])
        : "r"(a[0]), "r"(a[1]), "r"(a[2]), "r"(a[3]), "r"(b0), "r"(b1));
}

__device__ __forceinline__ void ldmx4(uint32_t r[4], uint32_t addr) {
    asm volatile("ldmatrix.sync.aligned.m8n8.x4.shared.b16 {%0,%1,%2,%3}, [%4];"
                 : "=r"(r[0]), "=r"(r[1]), "=r"(r[2]), "=r"(r[3]) : "r"(addr));
}
__device__ __forceinline__ void ldmx4t(uint32_t r[4], uint32_t addr) {
    asm volatile("ldmatrix.sync.aligned.m8n8.x4.trans.shared.b16 {%0,%1,%2,%3}, [%4];"
                 : "=r"(r[0]), "=r"(r[1]), "=r"(r[2]), "=r"(r[3]) : "r"(addr));
}

__device__ __forceinline__ uint32_t packh2(float a, float b) {
    __half2 h = __floats2half2_rn(a, b);
    return *(uint32_t*)&h;
}

__device__ __forceinline__ uint32_t pack_bf2(float a, float b) {
    __nv_bfloat162 t = __floats2bfloat162_rn(a, b);
    return *(uint32_t*)&t;
}
__device__ __forceinline__ float bf_hi(float x) {
    return __bfloat162float(__float2bfloat16_rn(x));
}

// ---------------------------------------------------------------------------
// Projection GEMM, bf16x3 split — unchanged from the measured R7 win.
// ---------------------------------------------------------------------------
__global__ __launch_bounds__(128) void proj_kernel(
    const float* __restrict__ x,
    const float* __restrict__ Wq,
    const float* __restrict__ Wk,
    const float* __restrict__ Wv)
{
    __shared__ uint32_t Xh[PRT * XSTR], Xl[PRT * XSTR];
    __shared__ uint32_t Wh[HH * XSTR],  Wl[HH * XSTR];

    const int wsel = blockIdx.y;
    const float* W  = (wsel == 0) ? Wq : (wsel == 1) ? Wk : Wv;
    float* dst      = (wsel == 0) ? g_q : (wsel == 1) ? g_k : g_v;

    const int tid  = threadIdx.x;
    const int lane = tid & 31, warp = tid >> 5;
    const int r = lane >> 2, c = lane & 3;
    const int w16 = warp * 16;
    const size_t row0 = (size_t)blockIdx.x * PRT;

    float acc[8][4];
#pragma unroll
    for (int j = 0; j < 8; ++j)
#pragma unroll
        for (int i = 0; i < 4; ++i) acc[j][i] = 0.f;

    for (int kb = 0; kb < CC; kb += PKC) {
        if (kb) __syncthreads();
#pragma unroll
        for (int it = 0; it < 8; ++it) {
            int f = it * 128 + tid;
            int row = f >> 4, cf = (f & 15) * 4;
            float4 v = *(const float4*)&x[(row0 + row) * CC + kb + cf];
            float hx = bf_hi(v.x), hy = bf_hi(v.y), hz = bf_hi(v.z), hw = bf_hi(v.w);
            uint2 hi = {pack_bf2(hx, hy), pack_bf2(hz, hw)};
            uint2 lo = {pack_bf2(v.x - hx, v.y - hy), pack_bf2(v.z - hz, v.w - hw)};
            int p = row * XSTR + cf / 2;
            *(uint2*)&Xh[p] = hi;
            *(uint2*)&Xl[p] = lo;
        }
#pragma unroll
        for (int it = 0; it < 4; ++it) {
            int idx = it * 128 + tid;
            int kp = idx >> 4, n0 = (idx & 15) * 4;
            float4 e = *(const float4*)&W[(kb + 2 * kp)     * HH + n0];
            float4 o = *(const float4*)&W[(kb + 2 * kp + 1) * HH + n0];
            float he[4] = {bf_hi(e.x), bf_hi(e.y), bf_hi(e.z), bf_hi(e.w)};
            float ho[4] = {bf_hi(o.x), bf_hi(o.y), bf_hi(o.z), bf_hi(o.w)};
            float ev[4] = {e.x, e.y, e.z, e.w}, ov[4] = {o.x, o.y, o.z, o.w};
#pragma unroll
            for (int i = 0; i < 4; ++i) {
                Wh[(n0 + i) * XSTR + kp] = pack_bf2(he[i], ho[i]);
                Wl[(n0 + i) * XSTR + kp] = pack_bf2(ev[i] - he[i], ov[i] - ho[i]);
            }
        }
        __syncthreads();

#pragma unroll
        for (int ks = 0; ks < 4; ++ks) {
            const int kp0 = 8 * ks;
            uint32_t ah[4], al[4];
            ah[0] = Xh[(w16 + r)     * XSTR + kp0 + c];
            ah[1] = Xh[(w16 + r + 8) * XSTR + kp0 + c];
            ah[2] = Xh[(w16 + r)     * XSTR + kp0 + c + 4];
            ah[3] = Xh[(w16 + r + 8) * XSTR + kp0 + c + 4];
            al[0] = Xl[(w16 + r)     * XSTR + kp0 + c];
            al[1] = Xl[(w16 + r + 8) * XSTR + kp0 + c];
            al[2] = Xl[(w16 + r)     * XSTR + kp0 + c + 4];
            al[3] = Xl[(w16 + r + 8) * XSTR + kp0 + c + 4];
#pragma unroll
            for (int j = 0; j < 8; ++j) {
                const int nrow = (8 * j + r) * XSTR + kp0;
                uint32_t bh0 = Wh[nrow + c], bh1 = Wh[nrow + c + 4];
                uint32_t bl0 = Wl[nrow + c], bl1 = Wl[nrow + c + 4];
                mma_bf16(acc[j], ah, bh0, bh1);
                mma_bf16(acc[j], ah, bl0, bl1);
                mma_bf16(acc[j], al, bh0, bh1);
            }
        }
    }

#pragma unroll
    for (int j = 0; j < 8; ++j) {
        float2 o0 = {acc[j][0], acc[j][1]};
        float2 o1 = {acc[j][2], acc[j][3]};
        *(float2*)&dst[(row0 + w16 + r)     * HH + 8 * j + 2 * c] = o0;
        *(float2*)&dst[(row0 + w16 + r + 8) * HH + 8 * j + 2 * c] = o1;
    }
}

// ---------------------------------------------------------------------------
// Flash attention, fp16 m16n8k16 + ldmatrix. 4 warps, Q tile 64, K tile 64.
// K/V/Q fp16 in smem (half the crossbar bytes of tf32); V fragments via
// ldmatrix.trans (no transpose staging); P stays in registers (S D-fragment
// packs exactly into the PV A-fragment). fp16-RN error <= previous tf32-trunc.
// ---------------------------------------------------------------------------
__global__ __launch_bounds__(128, 4) void attn_kernel(
    float* __restrict__ out, float scale)
{
    extern __shared__ char sm[];
    // [0, TILE_SM)          : Q  (64 rows x 144 B)
    // [TILE_SM, 2*TILE_SM)  : K
    // [2*TILE_SM, 3*TILE_SM): V
    const uint32_t sbase = (uint32_t)__cvta_generic_to_shared(sm);

    const int b = blockIdx.y, qtile = blockIdx.x;
    const int tid  = threadIdx.x;
    const int lane = tid & 31, warp = tid >> 5;
    const int r = lane >> 2, c = lane & 3;
    const int w16 = warp * 16;

    // ---- stage Q (scaled, fp16) ----
    {
        const float* qg = g_q + ((size_t)b * TT + (size_t)qtile * AQ) * HH;
#pragma unroll
        for (int it = 0; it < 8; ++it) {
            int f = it * 128 + tid;
            int row = f >> 4, cf = (f & 15) * 4;
            float4 v = *(const float4*)&qg[row * HH + cf];
            uint2 h = {packh2(v.x * scale, v.y * scale),
                       packh2(v.z * scale, v.w * scale)};
            *(uint2*)(sm + row * KROW + cf * 2) = h;
        }
    }
    __syncthreads();

    // ---- preload Q A-fragments: 4 k16-steps x 4 regs via ldmatrix.x4 ----
    // tiles: {rows+0,k+0},{rows+8,k+0},{rows+0,k+8},{rows+8,k+8} = a0..a3
    uint32_t qf[4][4];
    {
        uint32_t qa0 = sbase + (w16 + (lane & 7) + ((lane >> 3) & 1) * 8) * KROW
                     + ((lane >> 4) & 1) * 16;
#pragma unroll
        for (int t = 0; t < 4; ++t) ldmx4(qf[t], qa0 + t * 32);
    }

    float O[8][4];
#pragma unroll
    for (int j = 0; j < 8; ++j)
#pragma unroll
        for (int i = 0; i < 4; ++i) O[j][i] = 0.f;
    float m0 = -1e30f, m1 = -1e30f, l0 = 0.f, l1 = 0.f;

    const int row0g = qtile * AQ + w16 + r;
    const int row1g = row0g + 8;

    // per-thread ldmatrix base addresses (loop-invariant)
    // K (non-trans): tiles {(j,k0),(j,k8),(j+1,k0),(j+1,k8)}
    const uint32_t ka0 = sbase + TILE_SM
        + ((lane & 7) + ((lane >> 4) & 1) * 8) * KROW + ((lane >> 3) & 1) * 16;
    // V (trans): tiles {(key0,dj),(key8,dj),(key0,dj+1),(key8,dj+1)}
    const uint32_t va0 = sbase + 2 * TILE_SM
        + ((lane & 7) + ((lane >> 3) & 1) * 8) * KROW + ((lane >> 4) & 1) * 16;

    for (int kt = 0; kt <= qtile; ++kt) {
        const int kbase = kt * AKT;
        if (kt) __syncthreads();          // prev tile's compute done
        // ---- stage K,V (fp16) ----
        {
            const float* kg = g_k + ((size_t)b * TT + kbase) * HH;
            const float* vg = g_v + ((size_t)b * TT + kbase) * HH;
#pragma unroll
            for (int it = 0; it < 8; ++it) {
                int f = it * 128 + tid;
                int row = f >> 4, cf = (f & 15) * 4;
                float4 kv = *(const float4*)&kg[row * HH + cf];
                float4 vv = *(const float4*)&vg[row * HH + cf];
                uint2 kh = {packh2(kv.x, kv.y), packh2(kv.z, kv.w)};
                uint2 vh = {packh2(vv.x, vv.y), packh2(vv.z, vv.w)};
                *(uint2*)(sm + TILE_SM     + row * KROW + cf * 2) = kh;
                *(uint2*)(sm + 2 * TILE_SM + row * KROW + cf * 2) = vh;
            }
        }
        __syncthreads();

        // ---- S = Q @ K^T : 4 k16-steps x 4 j-pairs ----
        float S[8][4];
#pragma unroll
        for (int j = 0; j < 8; ++j)
#pragma unroll
            for (int i = 0; i < 4; ++i) S[j][i] = 0.f;

#pragma unroll
        for (int t = 0; t < 4; ++t) {
#pragma unroll
            for (int jp = 0; jp < 4; ++jp) {
                uint32_t kb[4];
                ldmx4(kb, ka0 + jp * (16 * KROW) + t * 32);
                mma_f16(S[2 * jp],     qf[t], kb[0], kb[1]);
                mma_f16(S[2 * jp + 1], qf[t], kb[2], kb[3]);
            }
        }

        // ---- causal mask (diagonal tile only) ----
        if (kt == qtile) {
#pragma unroll
            for (int j = 0; j < 8; ++j) {
                int col = kbase + 8 * j + 2 * c;
                if (col     > row0g) S[j][0] = -1e30f;
                if (col + 1 > row0g) S[j][1] = -1e30f;
                if (col     > row1g) S[j][2] = -1e30f;
                if (col + 1 > row1g) S[j][3] = -1e30f;
            }
        }

        // ---- online softmax (rows split across 4 lanes, shfl reduce) ----
        float mt0 = -1e30f, mt1 = -1e30f;
#pragma unroll
        for (int j = 0; j < 8; ++j) {
            mt0 = fmaxf(mt0, fmaxf(S[j][0], S[j][1]));
            mt1 = fmaxf(mt1, fmaxf(S[j][2], S[j][3]));
        }
#pragma unroll
        for (int off = 1; off < 4; off <<= 1) {
            mt0 = fmaxf(mt0, __shfl_xor_sync(0xffffffffu, mt0, off));
            mt1 = fmaxf(mt1, __shfl_xor_sync(0xffffffffu, mt1, off));
        }
        const float mn0 = fmaxf(m0, mt0), mn1 = fmaxf(m1, mt1);
        const float cr0 = __expf(m0 - mn0), cr1 = __expf(m1 - mn1);
        m0 = mn0; m1 = mn1;

        float ls0 = 0.f, ls1 = 0.f;
#pragma unroll
        for (int j = 0; j < 8; ++j) {
            S[j][0] = __expf(S[j][0] - mn0);
            S[j][1] = __expf(S[j][1] - mn0);
            S[j][2] = __expf(S[j][2] - mn1);
            S[j][3] = __expf(S[j][3] - mn1);
            ls0 += S[j][0] + S[j][1];
            ls1 += S[j][2] + S[j][3];
        }
#pragma unroll
        for (int off = 1; off < 4; off <<= 1) {
            ls0 += __shfl_xor_sync(0xffffffffu, ls0, off);
            ls1 += __shfl_xor_sync(0xffffffffu, ls1, off);
        }
        l0 = l0 * cr0 + ls0;
        l1 = l1 * cr1 + ls1;
#pragma unroll
        for (int j = 0; j < 8; ++j) {
            O[j][0] *= cr0; O[j][1] *= cr0;
            O[j][2] *= cr1; O[j][3] *= cr1;
        }

        // ---- pack P into fp16 A-fragments (register-resident, no smem) ----
        uint32_t P16[4][4];
#pragma unroll
        for (int u = 0; u < 4; ++u) {
            P16[u][0] = packh2(S[2 * u][0],     S[2 * u][1]);
            P16[u][1] = packh2(S[2 * u][2],     S[2 * u][3]);
            P16[u][2] = packh2(S[2 * u + 1][0], S[2 * u + 1][1]);
            P16[u][3] = packh2(S[2 * u + 1][2], S[2 * u + 1][3]);
        }

        // ---- O += P @ V : 4 k16-steps (keys) x 4 d-pairs, V via ldmatrix.trans
#pragma unroll
        for (int u = 0; u < 4; ++u) {
#pragma unroll
            for (int jp = 0; jp < 4; ++jp) {
                uint32_t vb[4];
                ldmx4t(vb, va0 + u * (16 * KROW) + jp * 32);
                mma_f16(O[2 * jp],     P16[u], vb[0], vb[1]);
                mma_f16(O[2 * jp + 1], P16[u], vb[2], vb[3]);
            }
        }
    }

    // ---- normalize + store ----
    const float inv0 = 1.f / l0, inv1 = 1.f / l1;
    float* og = out + ((size_t)b * TT + (size_t)qtile * AQ) * HH;
#pragma unroll
    for (int j = 0; j < 8; ++j) {
        float2 o0 = {O[j][0] * inv0, O[j][1] * inv0};
        float2 o1 = {O[j][2] * inv1, O[j][3] * inv1};
        *(float2*)&og[(w16 + r)     * HH + 8 * j + 2 * c] = o0;
        *(float2*)&og[(w16 + r + 8) * HH + 8 * j + 2 * c] = o1;
    }
}

// ---------------------------------------------------------------------------
extern "C" void kernel_launch(void* const* d_in, const int* in_sizes, int n_in,
                              void* d_out, int out_size)
{
    const float* x  = (const float*)d_in[0];
    const float* Wq = (const float*)d_in[1];
    const float* Wk = (const float*)d_in[2];
    const float* Wv = (const float*)d_in[3];
    float* out = (float*)d_out;

    const float scale = (float)pow(256.0, -0.666);

    cudaFuncSetAttribute(attn_kernel,
                         cudaFuncAttributeMaxDynamicSharedMemorySize, ATT_SMEM);

    dim3 pgrid((BB * TT) / PRT, 3);
    proj_kernel<<<pgrid, 128>>>(x, Wq, Wk, Wv);

    dim3 agrid(TT / AQ, BB);
    attn_kernel<<<agrid, 128, ATT_SMEM>>>(out, scale);
}

// round 12
// speedup vs baseline: 1.9074x; 1.4063x over previous
#include <cuda_runtime.h>
#include <cuda_fp16.h>
#include <math.h>
#include <stdint.h>

#define BB 32
#define TT 1024
#define CC 256
#define HH 64

// ---------------- attention tiling (fp16 mma + ldmatrix) ----------------
#define AQ 64            // q rows per CTA (16 per warp, 4 warps)
#define AKT 64           // keys per tile
#define KROW 144         // bytes per smem row: 64 fp16 + 16 pad
#define TILE_SM (64 * KROW)              // 9216 B per tile buffer
#define ATT_SMEM (3 * TILE_SM)           // Q + K + V = 27648 B

// ---------------- projection tiling (single-pass fp16 MMA) --------------
#define PRT 64
#define PKC 64
#define XSTR 36          // row stride in uint32 (32 half2 pairs + 4 pad)

// q/k/v stored as fp16 (attention consumes fp16 anyway — no extra rounding)
__device__ __half g_q[BB * TT * HH];
__device__ __half g_k[BB * TT * HH];
__device__ __half g_v[BB * TT * HH];

// ---------------------------------------------------------------------------
__device__ __forceinline__ void mma_f16(float d[4], const uint32_t a[4],
                                        const uint32_t b0, const uint32_t b1) {
    asm("mma.sync.aligned.m16n8k16.row.col.f32.f16.f16.f32 "
        "{%0,%1,%2,%3}, {%4,%5,%6,%7}, {%8,%9}, {%0,%1,%2,%3};"
        : "+f"(d[0]), "+f"(d[1]), "+f"(d[2]), "+f"(d[3])
        : "r"(a[0]), "r"(a[1]), "r"(a[2]), "r"(a[3]), "r"(b0), "r"(b1));
}

__device__ __forceinline__ void ldmx4(uint32_t r[4], uint32_t addr) {
    asm volatile("ldmatrix.sync.aligned.m8n8.x4.shared.b16 {%0,%1,%2,%3}, [%4];"
                 : "=r"(r[0]), "=r"(r[1]), "=r"(r[2]), "=r"(r[3]) : "r"(addr));
}
__device__ __forceinline__ void ldmx4t(uint32_t r[4], uint32_t addr) {
    asm volatile("ldmatrix.sync.aligned.m8n8.x4.trans.shared.b16 {%0,%1,%2,%3}, [%4];"
                 : "=r"(r[0]), "=r"(r[1]), "=r"(r[2]), "=r"(r[3]) : "r"(addr));
}

__device__ __forceinline__ uint32_t packh2(float a, float b) {
    __half2 h = __floats2half2_rn(a, b);
    return *(uint32_t*)&h;
}

// ---------------------------------------------------------------------------
// Projection GEMM, single-pass fp16 (attention rounds to fp16 anyway).
// X[32768,256] @ W[256,64], 3 matrices via blockIdx.y. Softmax scale folded
// into Wq. Output stored fp16. CTA = 64x64 tile, 4 warps each m=16 n=64.
// ---------------------------------------------------------------------------
__global__ __launch_bounds__(128) void proj_kernel(
    const float* __restrict__ x,
    const float* __restrict__ Wq,
    const float* __restrict__ Wk,
    const float* __restrict__ Wv,
    float scale)
{
    __shared__ uint32_t Xs[PRT * XSTR];   // rows x kpairs (fp16x2)
    __shared__ uint32_t Ws[HH * XSTR];    // n x kpairs    (fp16x2, transposed)

    const int wsel = blockIdx.y;
    const float* W   = (wsel == 0) ? Wq : (wsel == 1) ? Wk : Wv;
    __half* dst      = (wsel == 0) ? g_q : (wsel == 1) ? g_k : g_v;
    const float ws   = (wsel == 0) ? scale : 1.f;

    const int tid  = threadIdx.x;
    const int lane = tid & 31, warp = tid >> 5;
    const int r = lane >> 2, c = lane & 3;
    const int w16 = warp * 16;
    const size_t row0 = (size_t)blockIdx.x * PRT;

    float acc[8][4];
#pragma unroll
    for (int j = 0; j < 8; ++j)
#pragma unroll
        for (int i = 0; i < 4; ++i) acc[j][i] = 0.f;

    for (int kb = 0; kb < CC; kb += PKC) {
        if (kb) __syncthreads();
        // ---- stage X chunk: 64 rows x 64 k (fp16) ----
#pragma unroll
        for (int it = 0; it < 8; ++it) {
            int f = it * 128 + tid;
            int row = f >> 4, cf = (f & 15) * 4;
            float4 v = *(const float4*)&x[(row0 + row) * CC + kb + cf];
            uint2 h = {packh2(v.x, v.y), packh2(v.z, v.w)};
            *(uint2*)&Xs[row * XSTR + cf / 2] = h;
        }
        // ---- stage W chunk transposed: gmem [k][n] -> smem [n][kpair] ----
#pragma unroll
        for (int it = 0; it < 4; ++it) {
            int idx = it * 128 + tid;
            int kp = idx >> 4, n0 = (idx & 15) * 4;
            float4 e = *(const float4*)&W[(kb + 2 * kp)     * HH + n0];
            float4 o = *(const float4*)&W[(kb + 2 * kp + 1) * HH + n0];
            float ev[4] = {e.x * ws, e.y * ws, e.z * ws, e.w * ws};
            float ov[4] = {o.x * ws, o.y * ws, o.z * ws, o.w * ws};
#pragma unroll
            for (int i = 0; i < 4; ++i)
                Ws[(n0 + i) * XSTR + kp] = packh2(ev[i], ov[i]);
        }
        __syncthreads();

        // ---- MMA: 4 k16-steps x 8 n-tiles ----
#pragma unroll
        for (int ks = 0; ks < 4; ++ks) {
            const int kp0 = 8 * ks;
            uint32_t a[4];
            a[0] = Xs[(w16 + r)     * XSTR + kp0 + c];
            a[1] = Xs[(w16 + r + 8) * XSTR + kp0 + c];
            a[2] = Xs[(w16 + r)     * XSTR + kp0 + c + 4];
            a[3] = Xs[(w16 + r + 8) * XSTR + kp0 + c + 4];
#pragma unroll
            for (int j = 0; j < 8; ++j) {
                const int nrow = (8 * j + r) * XSTR + kp0;
                mma_f16(acc[j], a, Ws[nrow + c], Ws[nrow + c + 4]);
            }
        }
    }

    // ---- store fp16 ----
#pragma unroll
    for (int j = 0; j < 8; ++j) {
        *(uint32_t*)&dst[(row0 + w16 + r)     * HH + 8 * j + 2 * c] =
            packh2(acc[j][0], acc[j][1]);
        *(uint32_t*)&dst[(row0 + w16 + r + 8) * HH + 8 * j + 2 * c] =
            packh2(acc[j][2], acc[j][3]);
    }
}

// ---------------------------------------------------------------------------
// Flash attention, fp16 m16n8k16 + ldmatrix. Staging is now a pure 16B copy
// (q/k/v already fp16 in gmem, scale folded into Wq). P register-resident.
// ---------------------------------------------------------------------------
__global__ __launch_bounds__(128, 4) void attn_kernel(float* __restrict__ out)
{
    extern __shared__ char sm[];
    // [0, TILE_SM): Q   [TILE_SM, 2*TILE_SM): K   [2*TILE_SM, 3*TILE_SM): V
    const uint32_t sbase = (uint32_t)__cvta_generic_to_shared(sm);

    const int b = blockIdx.y, qtile = blockIdx.x;
    const int tid  = threadIdx.x;
    const int lane = tid & 31, warp = tid >> 5;
    const int r = lane >> 2, c = lane & 3;
    const int w16 = warp * 16;

    // ---- stage Q: pure copy, 64 rows x 128 B ----
    {
        const uint4* qg = (const uint4*)(g_q + ((size_t)b * TT + (size_t)qtile * AQ) * HH);
#pragma unroll
        for (int it = 0; it < 4; ++it) {
            int f = it * 128 + tid;            // 512 uint4
            int row = f >> 3, u = f & 7;
            *(uint4*)(sm + row * KROW + u * 16) = qg[row * 8 + u];
        }
    }
    __syncthreads();

    // ---- preload Q A-fragments via ldmatrix.x4 ----
    uint32_t qf[4][4];
    {
        uint32_t qa0 = sbase + (w16 + (lane & 7) + ((lane >> 3) & 1) * 8) * KROW
                     + ((lane >> 4) & 1) * 16;
#pragma unroll
        for (int t = 0; t < 4; ++t) ldmx4(qf[t], qa0 + t * 32);
    }

    float O[8][4];
#pragma unroll
    for (int j = 0; j < 8; ++j)
#pragma unroll
        for (int i = 0; i < 4; ++i) O[j][i] = 0.f;
    float m0 = -1e30f, m1 = -1e30f, l0 = 0.f, l1 = 0.f;

    const int row0g = qtile * AQ + w16 + r;
    const int row1g = row0g + 8;

    const uint32_t ka0 = sbase + TILE_SM
        + ((lane & 7) + ((lane >> 4) & 1) * 8) * KROW + ((lane >> 3) & 1) * 16;
    const uint32_t va0 = sbase + 2 * TILE_SM
        + ((lane & 7) + ((lane >> 3) & 1) * 8) * KROW + ((lane >> 4) & 1) * 16;

    for (int kt = 0; kt <= qtile; ++kt) {
        const int kbase = kt * AKT;
        if (kt) __syncthreads();
        // ---- stage K,V: pure copies ----
        {
            const uint4* kg = (const uint4*)(g_k + ((size_t)b * TT + kbase) * HH);
            const uint4* vg = (const uint4*)(g_v + ((size_t)b * TT + kbase) * HH);
#pragma unroll
            for (int it = 0; it < 4; ++it) {
                int f = it * 128 + tid;
                int row = f >> 3, u = f & 7;
                *(uint4*)(sm + TILE_SM     + row * KROW + u * 16) = kg[row * 8 + u];
                *(uint4*)(sm + 2 * TILE_SM + row * KROW + u * 16) = vg[row * 8 + u];
            }
        }
        __syncthreads();

        // ---- S = Q @ K^T ----
        float S[8][4];
#pragma unroll
        for (int j = 0; j < 8; ++j)
#pragma unroll
            for (int i = 0; i < 4; ++i) S[j][i] = 0.f;

#pragma unroll
        for (int t = 0; t < 4; ++t) {
#pragma unroll
            for (int jp = 0; jp < 4; ++jp) {
                uint32_t kb[4];
                ldmx4(kb, ka0 + jp * (16 * KROW) + t * 32);
                mma_f16(S[2 * jp],     qf[t], kb[0], kb[1]);
                mma_f16(S[2 * jp + 1], qf[t], kb[2], kb[3]);
            }
        }

        // ---- causal mask (diagonal tile only) ----
        if (kt == qtile) {
#pragma unroll
            for (int j = 0; j < 8; ++j) {
                int col = kbase + 8 * j + 2 * c;
                if (col     > row0g) S[j][0] = -1e30f;
                if (col + 1 > row0g) S[j][1] = -1e30f;
                if (col     > row1g) S[j][2] = -1e30f;
                if (col + 1 > row1g) S[j][3] = -1e30f;
            }
        }

        // ---- online softmax ----
        float mt0 = -1e30f, mt1 = -1e30f;
#pragma unroll
        for (int j = 0; j < 8; ++j) {
            mt0 = fmaxf(mt0, fmaxf(S[j][0], S[j][1]));
            mt1 = fmaxf(mt1, fmaxf(S[j][2], S[j][3]));
        }
#pragma unroll
        for (int off = 1; off < 4; off <<= 1) {
            mt0 = fmaxf(mt0, __shfl_xor_sync(0xffffffffu, mt0, off));
            mt1 = fmaxf(mt1, __shfl_xor_sync(0xffffffffu, mt1, off));
        }
        const float mn0 = fmaxf(m0, mt0), mn1 = fmaxf(m1, mt1);
        const float cr0 = __expf(m0 - mn0), cr1 = __expf(m1 - mn1);
        m0 = mn0; m1 = mn1;

        float ls0 = 0.f, ls1 = 0.f;
#pragma unroll
        for (int j = 0; j < 8; ++j) {
            S[j][0] = __expf(S[j][0] - mn0);
            S[j][1] = __expf(S[j][1] - mn0);
            S[j][2] = __expf(S[j][2] - mn1);
            S[j][3] = __expf(S[j][3] - mn1);
            ls0 += S[j][0] + S[j][1];
            ls1 += S[j][2] + S[j][3];
        }
#pragma unroll
        for (int off = 1; off < 4; off <<= 1) {
            ls0 += __shfl_xor_sync(0xffffffffu, ls0, off);
            ls1 += __shfl_xor_sync(0xffffffffu, ls1, off);
        }
        l0 = l0 * cr0 + ls0;
        l1 = l1 * cr1 + ls1;
#pragma unroll
        for (int j = 0; j < 8; ++j) {
            O[j][0] *= cr0; O[j][1] *= cr0;
            O[j][2] *= cr1; O[j][3] *= cr1;
        }

        // ---- pack P into fp16 A-fragments (register-resident) ----
        uint32_t P16[4][4];
#pragma unroll
        for (int u = 0; u < 4; ++u) {
            P16[u][0] = packh2(S[2 * u][0],     S[2 * u][1]);
            P16[u][1] = packh2(S[2 * u][2],     S[2 * u][3]);
            P16[u][2] = packh2(S[2 * u + 1][0], S[2 * u + 1][1]);
            P16[u][3] = packh2(S[2 * u + 1][2], S[2 * u + 1][3]);
        }

        // ---- O += P @ V (V via ldmatrix.trans) ----
#pragma unroll
        for (int u = 0; u < 4; ++u) {
#pragma unroll
            for (int jp = 0; jp < 4; ++jp) {
                uint32_t vb[4];
                ldmx4t(vb, va0 + u * (16 * KROW) + jp * 32);
                mma_f16(O[2 * jp],     P16[u], vb[0], vb[1]);
                mma_f16(O[2 * jp + 1], P16[u], vb[2], vb[3]);
            }
        }
    }

    // ---- normalize + store ----
    const float inv0 = 1.f / l0, inv1 = 1.f / l1;
    float* og = out + ((size_t)b * TT + (size_t)qtile * AQ) * HH;
#pragma unroll
    for (int j = 0; j < 8; ++j) {
        float2 o0 = {O[j][0] * inv0, O[j][1] * inv0};
        float2 o1 = {O[j][2] * inv1, O[j][3] * inv1};
        *(float2*)&og[(w16 + r)     * HH + 8 * j + 2 * c] = o0;
        *(float2*)&og[(w16 + r + 8) * HH + 8 * j + 2 * c] = o1;
    }
}

// ---------------------------------------------------------------------------
extern "C" void kernel_launch(void* const* d_in, const int* in_sizes, int n_in,
                              void* d_out, int out_size)
{
    const float* x  = (const float*)d_in[0];
    const float* Wq = (const float*)d_in[1];
    const float* Wk = (const float*)d_in[2];
    const float* Wv = (const float*)d_in[3];
    float* out = (float*)d_out;

    const float scale = (float)pow(256.0, -0.666);

    cudaFuncSetAttribute(attn_kernel,
                         cudaFuncAttributeMaxDynamicSharedMemorySize, ATT_SMEM);

    dim3 pgrid((BB * TT) / PRT, 3);
    proj_kernel<<<pgrid, 128>>>(x, Wq, Wk, Wv, scale);

    dim3 agrid(TT / AQ, BB);
    attn_kernel<<<agrid, 128, ATT_SMEM>>>(out);
}